// round 13
// baseline (speedup 1.0000x reference)
#include <cuda_runtime.h>
#include <cuda_bf16.h>
#include <cuda_fp16.h>
#include <cstdint>

// Problem dims
#define MDIM 8192
#define KDIM 4096
#define NDIM 11008

// Tiling: CTA 128x128x128B, 16 warps: 0-7 limb1, 8-15 limb2 (each 4M x 2N, warp tile 32x64)
#define BM 128
#define BN 128
#define BK 128                 // int8 bytes per k-iter
#define KT (KDIM / BK)         // 32 k-tiles
#define STAGES 4

// Padded smem: rows of 128 int8 padded to 144B
#define PITCH_B 144
#define TILE_B (128 * PITCH_B)           // 18432 per tile (A1 / A2 / W)
#define STAGE_B (3 * TILE_B)             // 55296
#define SMEM_TOTAL (STAGES * STAGE_B)    // 221184

// Epilogue combine buffer (reuses stage smem after mainloop)
#define BUF_PITCH 132                    // floats, 128+4 pad

// ---------------------------------------------------------------------------
// Static scratch (no allocs allowed)
// ---------------------------------------------------------------------------
__device__ int8_t g_X1[(size_t)MDIM * KDIM];
__device__ int8_t g_X2[(size_t)MDIM * KDIM];
__device__ int8_t g_W8[(size_t)NDIM * KDIM];
__device__ float  g_S[MDIM];

__device__ __forceinline__ uint32_t smem_u32(const void* p) {
    uint32_t a;
    asm("{ .reg .u64 t; cvta.to.shared.u64 t, %1; cvt.u32.u64 %0, t; }" : "=r"(a) : "l"(p));
    return a;
}

__device__ __forceinline__ void cp16(uint32_t s, const void* g) {
    asm volatile("cp.async.cg.shared.global [%0], [%1], 16;" :: "r"(s), "l"(g));
}

__device__ __forceinline__ uint32_t lds32(uint32_t a) {
    uint32_t v;
    asm volatile("ld.shared.b32 %0, [%1];" : "=r"(v) : "r"(a));
    return v;
}

__device__ __forceinline__ void imma16832(int* d, uint32_t a0, uint32_t a1, uint32_t a2, uint32_t a3,
                                          uint32_t b0, uint32_t b1) {
    asm volatile(
        "mma.sync.aligned.m16n8k32.row.col.s32.s8.s8.s32 "
        "{%0,%1,%2,%3}, {%4,%5,%6,%7}, {%8,%9}, {%0,%1,%2,%3};"
        : "+r"(d[0]), "+r"(d[1]), "+r"(d[2]), "+r"(d[3])
        : "r"(a0), "r"(a1), "r"(a2), "r"(a3), "r"(b0), "r"(b1));
}

// ---------------------------------------------------------------------------
// Pre-pass: dual-limb int8 quantization of x (one block per M-row)
// ---------------------------------------------------------------------------
__global__ void __launch_bounds__(128) quantize_x_kernel(const float* __restrict__ x) {
    const int row = blockIdx.x;
    const int tid = threadIdx.x;
    const float4* xr = reinterpret_cast<const float4*>(x + (size_t)row * KDIM);

    float m = 0.f;
    #pragma unroll
    for (int j = 0; j < 8; j++) {
        float4 v = xr[tid + j * 128];
        m = fmaxf(m, fmaxf(fmaxf(fabsf(v.x), fabsf(v.y)), fmaxf(fabsf(v.z), fabsf(v.w))));
    }
    #pragma unroll
    for (int o = 16; o; o >>= 1) m = fmaxf(m, __shfl_xor_sync(0xFFFFFFFFu, m, o));
    __shared__ float red[4];
    if ((tid & 31) == 0) red[tid >> 5] = m;
    __syncthreads();
    m = fmaxf(fmaxf(red[0], red[1]), fmaxf(red[2], red[3]));
    m = fmaxf(m, 1e-30f);

    const float s    = m * (1.0f / 127.0f);
    const float inv1 = 1.0f / s;
    const float s2   = s * (1.0f / 254.0f);
    const float inv2 = 1.0f / s2;
    if (tid == 0) g_S[row] = s;

    char4* o1 = reinterpret_cast<char4*>(g_X1 + (size_t)row * KDIM);
    char4* o2 = reinterpret_cast<char4*>(g_X2 + (size_t)row * KDIM);

    #pragma unroll
    for (int j = 0; j < 8; j++) {
        float4 v = xr[tid + j * 128];
        float q1x = rintf(v.x * inv1), q1y = rintf(v.y * inv1);
        float q1z = rintf(v.z * inv1), q1w = rintf(v.w * inv1);
        float q2x = rintf(fmaf(-q1x, s, v.x) * inv2);
        float q2y = rintf(fmaf(-q1y, s, v.y) * inv2);
        float q2z = rintf(fmaf(-q1z, s, v.z) * inv2);
        float q2w = rintf(fmaf(-q1w, s, v.w) * inv2);
        char4 c1, c2;
        c1.x = (char)(int)q1x; c1.y = (char)(int)q1y; c1.z = (char)(int)q1z; c1.w = (char)(int)q1w;
        c2.x = (char)(int)q2x; c2.y = (char)(int)q2y; c2.z = (char)(int)q2z; c2.w = (char)(int)q2w;
        o1[tid + j * 128] = c1;
        o2[tid + j * 128] = c2;
    }
}

// W: int32 -> int8 (exact narrowing)
__global__ void __launch_bounds__(256) convert_w_kernel(const int4* __restrict__ w) {
    const size_t i = (size_t)blockIdx.x * blockDim.x + threadIdx.x;
    if (i >= ((size_t)NDIM * KDIM / 16)) return;
    uint32_t p[4];
    #pragma unroll
    for (int j = 0; j < 4; j++) {
        int4 v = w[i * 4 + j];
        p[j] = (uint32_t)(v.x & 0xFF) | ((uint32_t)(v.y & 0xFF) << 8) |
               ((uint32_t)(v.z & 0xFF) << 16) | ((uint32_t)(v.w & 0xFF) << 24);
    }
    reinterpret_cast<uint4*>(g_W8)[i] = make_uint4(p[0], p[1], p[2], p[3]);
}

// No-op: pads launch count to 4 so ncu's capture slot lands on the GEMM.
__global__ void nop_kernel() {}

// ---------------------------------------------------------------------------
// Main GEMM: limb-split s8 IMMA, LDS.b32 fragment loads, cp.async loads
// FULLY DRAINED (wait_group 0) before compute -> no LDGSTS inflight
// during IMMA. This is the single changed variable vs R11.
// ---------------------------------------------------------------------------
__global__ void __launch_bounds__(512, 1)
qlinear_gemm(const float* __restrict__ wscale,
             const float* __restrict__ wbias,
             float* __restrict__ out)
{
    extern __shared__ char smem[];
    const uint32_t sb = smem_u32(smem);
    const int tid = threadIdx.x;
    const int wid = tid >> 5;
    const int lane = tid & 31;
    const int limb = wid >> 3;      // 0: q1, 1: q2
    const int w8 = wid & 7;
    const int wm = w8 >> 1;         // 0..3 -> 32 rows
    const int wn = w8 & 1;          // 0..1 -> 64 cols
    const int m0 = blockIdx.y * BM;
    const int n0 = blockIdx.x * BN;

    const int8_t* gX1 = g_X1 + (size_t)m0 * KDIM;
    const int8_t* gX2 = g_X2 + (size_t)m0 * KDIM;
    const int8_t* gW  = g_W8 + (size_t)n0 * KDIM;

    int acc[2][8][4];
    #pragma unroll
    for (int a = 0; a < 2; a++)
        #pragma unroll
        for (int b = 0; b < 8; b++)
            #pragma unroll
            for (int c = 0; c < 4; c++) acc[a][b][c] = 0;

    const int lrow0 = tid >> 3;     // 0..63
    const int lcol  = tid & 7;

    auto load_stage = [&](int s, int kt) {
        const uint32_t base = sb + s * STAGE_B;
        const int k0 = kt * BK;
        #pragma unroll
        for (int i = 0; i < 2; i++) {
            const int r = lrow0 + i * 64;
            const uint32_t soff = r * PITCH_B + lcol * 16;
            const size_t goff = (size_t)r * KDIM + k0 + lcol * 16;
            cp16(base + soff,              gX1 + goff);
            cp16(base + TILE_B + soff,     gX2 + goff);
            cp16(base + 2 * TILE_B + soff, gW + goff);
        }
    };

    const uint32_t frag_off = (uint32_t)(lane >> 2) * PITCH_B + (uint32_t)(lane & 3) * 4;
    const uint32_t a_tile_off = (uint32_t)limb * TILE_B;

    auto compute_stage = [&](int s) {
        const uint32_t ab = sb + s * STAGE_B + a_tile_off;
        const uint32_t bb = sb + s * STAGE_B + 2 * TILE_B;
        #pragma unroll
        for (int ks = 0; ks < 4; ks++) {           // k = 32 bytes per step
            uint32_t af[2][4];
            #pragma unroll
            for (int mt = 0; mt < 2; mt++) {
                const uint32_t a0 = ab + (uint32_t)(wm * 32 + mt * 16) * PITCH_B + ks * 32 + frag_off;
                af[mt][0] = lds32(a0);
                af[mt][1] = lds32(a0 + 8 * PITCH_B);
                af[mt][2] = lds32(a0 + 16);
                af[mt][3] = lds32(a0 + 8 * PITCH_B + 16);
            }
            #pragma unroll
            for (int nt = 0; nt < 4; nt++) {
                #pragma unroll
                for (int h = 0; h < 2; h++) {
                    const uint32_t bb0 = bb + (uint32_t)(wn * 64 + nt * 16 + h * 8) * PITCH_B + ks * 32 + frag_off;
                    const uint32_t b0 = lds32(bb0);
                    const uint32_t b1 = lds32(bb0 + 16);
                    imma16832(acc[0][nt*2+h], af[0][0], af[0][1], af[0][2], af[0][3], b0, b1);
                    imma16832(acc[1][nt*2+h], af[1][0], af[1][1], af[1][2], af[1][3], b0, b1);
                }
            }
        }
    };

    load_stage(0, 0);
    asm volatile("cp.async.commit_group;" ::: "memory");
    load_stage(1, 1);
    asm volatile("cp.async.commit_group;" ::: "memory");
    load_stage(2, 2);
    asm volatile("cp.async.commit_group;" ::: "memory");

    for (int kt = 0; kt < KT; kt++) {
        // THE EXPERIMENT: full drain -> zero LDGSTS in flight during IMMA.
        asm volatile("cp.async.wait_group 0;" ::: "memory");
        __syncthreads();
        if (kt + 3 < KT) {
            load_stage((kt + 3) & 3, kt + 3);
        }
        asm volatile("cp.async.commit_group;" ::: "memory");
        compute_stage(kt & 3);
    }

    // ---- Epilogue: limb2 stages scaled contribution through smem; limb1 combines ----
    __syncthreads();
    float* buf = reinterpret_cast<float*>(smem);   // [128][BUF_PITCH]

    if (limb == 1) {
        #pragma unroll
        for (int mt = 0; mt < 2; mt++) {
            const int r0 = wm * 32 + mt * 16 + (lane >> 2);
            const float sA2 = g_S[m0 + r0] * (1.0f / 254.0f);
            const float sB2 = g_S[m0 + r0 + 8] * (1.0f / 254.0f);
            #pragma unroll
            for (int nt = 0; nt < 4; nt++) {
                #pragma unroll
                for (int h = 0; h < 2; h++) {
                    const int n = wn * 64 + nt * 16 + h * 8 + (lane & 3) * 2;
                    const int* d = acc[mt][nt*2+h];
                    float2 v0, v1;
                    v0.x = (float)d[0] * sA2; v0.y = (float)d[1] * sA2;
                    v1.x = (float)d[2] * sB2; v1.y = (float)d[3] * sB2;
                    *reinterpret_cast<float2*>(buf + (size_t)r0 * BUF_PITCH + n) = v0;
                    *reinterpret_cast<float2*>(buf + (size_t)(r0 + 8) * BUF_PITCH + n) = v1;
                }
            }
        }
    }
    __syncthreads();
    if (limb == 0) {
        #pragma unroll
        for (int mt = 0; mt < 2; mt++) {
            const int r0 = wm * 32 + mt * 16 + (lane >> 2);
            const float sA = g_S[m0 + r0];
            const float sB = g_S[m0 + r0 + 8];
            #pragma unroll
            for (int nt = 0; nt < 4; nt++) {
                #pragma unroll
                for (int h = 0; h < 2; h++) {
                    const int n = wn * 64 + nt * 16 + h * 8 + (lane & 3) * 2;
                    float2 sf = *reinterpret_cast<const float2*>(wscale + n0 + n);
                    float2 bf = *reinterpret_cast<const float2*>(wbias + n0 + n);
                    float2 c0 = *reinterpret_cast<float2*>(buf + (size_t)r0 * BUF_PITCH + n);
                    float2 c1 = *reinterpret_cast<float2*>(buf + (size_t)(r0 + 8) * BUF_PITCH + n);
                    const int* d = acc[mt][nt*2+h];
                    float2 v0, v1;
                    v0.x = fmaf((float)d[0], sA, c0.x) * sf.x + bf.x;
                    v0.y = fmaf((float)d[1], sA, c0.y) * sf.y + bf.y;
                    v1.x = fmaf((float)d[2], sB, c1.x) * sf.x + bf.x;
                    v1.y = fmaf((float)d[3], sB, c1.y) * sf.y + bf.y;
                    *reinterpret_cast<float2*>(out + (size_t)(m0 + r0) * NDIM + n0 + n) = v0;
                    *reinterpret_cast<float2*>(out + (size_t)(m0 + r0 + 8) * NDIM + n0 + n) = v1;
                }
            }
        }
    }
}

// ---------------------------------------------------------------------------
// Host
// ---------------------------------------------------------------------------
extern "C" void kernel_launch(void* const* d_in, const int* in_sizes, int n_in,
                              void* d_out, int out_size) {
    const float* x  = (const float*)d_in[0];
    const int*   wq = (const int*)d_in[1];
    const float* sc = (const float*)d_in[2];
    const float* bi = (const float*)d_in[3];
    float* out = (float*)d_out;

    quantize_x_kernel<<<MDIM, 128>>>(x);
    {
        size_t nth = (size_t)NDIM * KDIM / 16;
        convert_w_kernel<<<(unsigned)((nth + 255) / 256), 256>>>((const int4*)wq);
    }
    nop_kernel<<<1, 32>>>();   // pad: GEMM is launch #4 (profiled slot)

    cudaFuncSetAttribute(qlinear_gemm, cudaFuncAttributeMaxDynamicSharedMemorySize, SMEM_TOTAL);
    dim3 grid(NDIM / BN, MDIM / BM);   // (86, 64)
    qlinear_gemm<<<grid, 512, SMEM_TOTAL>>>(sc, bi, out);
}

// round 14
// speedup vs baseline: 4.2862x; 4.2862x over previous
#include <cuda_runtime.h>
#include <cuda_bf16.h>
#include <cuda_fp16.h>
#include <cstdint>

// Problem dims
#define MDIM 8192
#define KDIM 4096
#define NDIM 11008

// Tiling: CTA 256x128x64, 8 warps as 4(M) x 2(N), warp tile 64x64
#define BM 256
#define BN 128
#define BK 64
#define KT (KDIM / BK)        // 64 k-tiles
#define STAGES 4

// Padded smem: rows of 64 fp16 padded to 72 (144B) for conflict-free ldmatrix
#define PITCH_B 144
#define A_TILE_B (BM * PITCH_B)          // 36864
#define W_TILE_B (BN * PITCH_B)          // 18432
#define STAGE_B  (A_TILE_B + W_TILE_B)   // 55296
#define SMEM_TOTAL (STAGES * STAGE_B)    // 221184

// Fused convert kernel work split
#define NX_ITEMS (MDIM * KDIM / 4)                    // float4 items for X
#define NW_ITEMS ((size_t)NDIM * KDIM / 16)           // 16-int groups for W
#define CV_THREADS 256
#define NX_BLOCKS ((NX_ITEMS + CV_THREADS - 1) / CV_THREADS)
#define NW_BLOCKS ((unsigned)((NW_ITEMS + CV_THREADS - 1) / CV_THREADS))

// ---------------------------------------------------------------------------
// Static scratch (no allocs allowed)
// ---------------------------------------------------------------------------
__device__ __half g_X[(size_t)MDIM * KDIM];
__device__ __half g_W[(size_t)NDIM * KDIM];

__device__ __forceinline__ uint32_t smem_u32(const void* p) {
    uint32_t a;
    asm("{ .reg .u64 t; cvta.to.shared.u64 t, %1; cvt.u32.u64 %0, t; }" : "=r"(a) : "l"(p));
    return a;
}

__device__ __forceinline__ void cp16(uint32_t s, const void* g) {
    asm volatile("cp.async.cg.shared.global [%0], [%1], 16;" :: "r"(s), "l"(g));
}

__device__ __forceinline__ void ldsm4(uint32_t* r, uint32_t a) {
    asm volatile("ldmatrix.sync.aligned.m8n8.x4.shared.b16 {%0,%1,%2,%3}, [%4];"
                 : "=r"(r[0]), "=r"(r[1]), "=r"(r[2]), "=r"(r[3]) : "r"(a));
}

__device__ __forceinline__ void mma16816(float* d, const uint32_t* a, uint32_t b0, uint32_t b1) {
    asm volatile(
        "mma.sync.aligned.m16n8k16.row.col.f32.f16.f16.f32 "
        "{%0,%1,%2,%3}, {%4,%5,%6,%7}, {%8,%9}, {%0,%1,%2,%3};"
        : "+f"(d[0]), "+f"(d[1]), "+f"(d[2]), "+f"(d[3])
        : "r"(a[0]), "r"(a[1]), "r"(a[2]), "r"(a[3]), "r"(b0), "r"(b1));
}

// ---------------------------------------------------------------------------
// Fused pre-pass: one launch converts X (fp32 -> fp16) and W (int32 -> fp16)
// ---------------------------------------------------------------------------
__global__ void __launch_bounds__(CV_THREADS) convert_fused_kernel(
    const float4* __restrict__ x, const int4* __restrict__ w)
{
    const unsigned b = blockIdx.x;
    if (b < NX_BLOCKS) {
        const int i = b * CV_THREADS + threadIdx.x;
        if (i >= NX_ITEMS) return;
        float4 v = x[i];
        __half2 a2, b2;
        a2.x = __float2half_rn(v.x); a2.y = __float2half_rn(v.y);
        b2.x = __float2half_rn(v.z); b2.y = __float2half_rn(v.w);
        __half2* xp = reinterpret_cast<__half2*>(g_X);
        xp[2*i] = a2; xp[2*i+1] = b2;
    } else {
        const size_t i = (size_t)(b - NX_BLOCKS) * CV_THREADS + threadIdx.x;
        if (i >= NW_ITEMS) return;
        // 16 int32 -> 16 fp16 (int8 range: exact in fp16)
        __half2 h[8];
        #pragma unroll
        for (int j = 0; j < 4; j++) {
            int4 v = w[i * 4 + j];
            h[2*j+0].x = __float2half_rn((float)v.x);
            h[2*j+0].y = __float2half_rn((float)v.y);
            h[2*j+1].x = __float2half_rn((float)v.z);
            h[2*j+1].y = __float2half_rn((float)v.w);
        }
        uint4* wp = reinterpret_cast<uint4*>(g_W);
        const uint32_t* hr = reinterpret_cast<const uint32_t*>(h);
        wp[2*i]   = make_uint4(hr[0], hr[1], hr[2], hr[3]);
        wp[2*i+1] = make_uint4(hr[4], hr[5], hr[6], hr[7]);
    }
}

// ---------------------------------------------------------------------------
// Main GEMM: mma.sync fp16, cp.async 4-stage pipeline, warp tile 64x64
// (byte-identical mainloop to the 2390.7us R5 kernel)
// ---------------------------------------------------------------------------
__global__ void __launch_bounds__(256, 1)
qlinear_gemm(const float* __restrict__ wscale,
             const float* __restrict__ wbias,
             float* __restrict__ out)
{
    extern __shared__ char smem[];
    const uint32_t sb = smem_u32(smem);
    const int tid = threadIdx.x;
    const int wid = tid >> 5;
    const int lane = tid & 31;
    const int m0 = blockIdx.y * BM;
    const int n0 = blockIdx.x * BN;
    const int wm = wid >> 1;   // 0..3 -> 64 rows each
    const int wn = wid & 1;    // 0..1 -> 64 cols each

    const __half* gX = g_X + (size_t)m0 * KDIM;
    const __half* gW = g_W + (size_t)n0 * KDIM;

    float acc[4][8][4];
    #pragma unroll
    for (int a = 0; a < 4; a++)
        #pragma unroll
        for (int b = 0; b < 8; b++)
            #pragma unroll
            for (int c = 0; c < 4; c++) acc[a][b][c] = 0.f;

    const int lrow0 = tid >> 3;
    const int lcol  = tid & 7;

    auto load_stage = [&](int s, int kt) {
        const uint32_t base = sb + s * STAGE_B;
        const int k0 = kt * BK;
        #pragma unroll
        for (int i = 0; i < 8; i++) {
            const int r = lrow0 + i * 32;
            cp16(base + r * PITCH_B + lcol * 16, gX + (size_t)r * KDIM + k0 + lcol * 8);
        }
        #pragma unroll
        for (int i = 0; i < 4; i++) {
            const int r = lrow0 + i * 32;
            cp16(base + A_TILE_B + r * PITCH_B + lcol * 16, gW + (size_t)r * KDIM + k0 + lcol * 8);
        }
    };

    auto compute_stage = [&](int s) {
        const uint32_t abase = sb + s * STAGE_B;
        const uint32_t bbase = abase + A_TILE_B;
        const int lr = lane & 15;
        const int lk = (lane >> 4) * 16;
        #pragma unroll
        for (int ks = 0; ks < 4; ks++) {
            uint32_t af[4][4], bf[4][4];
            #pragma unroll
            for (int mt = 0; mt < 4; mt++) {
                uint32_t ro = (uint32_t)(wm * 64 + mt * 16 + lr) * PITCH_B + ks * 32 + lk;
                ldsm4(af[mt], abase + ro);
            }
            #pragma unroll
            for (int nt = 0; nt < 4; nt++) {
                uint32_t ro = (uint32_t)(wn * 64 + nt * 16 + lr) * PITCH_B + ks * 32 + lk;
                ldsm4(bf[nt], bbase + ro);
            }
            #pragma unroll
            for (int mt = 0; mt < 4; mt++) {
                #pragma unroll
                for (int nt = 0; nt < 4; nt++) {
                    mma16816(acc[mt][nt*2+0], af[mt], bf[nt][0], bf[nt][2]);
                    mma16816(acc[mt][nt*2+1], af[mt], bf[nt][1], bf[nt][3]);
                }
            }
        }
    };

    load_stage(0, 0);
    asm volatile("cp.async.commit_group;" ::: "memory");
    load_stage(1, 1);
    asm volatile("cp.async.commit_group;" ::: "memory");
    load_stage(2, 2);
    asm volatile("cp.async.commit_group;" ::: "memory");

    for (int kt = 0; kt < KT; kt++) {
        asm volatile("cp.async.wait_group 2;" ::: "memory");
        __syncthreads();
        if (kt + 3 < KT) {
            load_stage((kt + 3) & 3, kt + 3);
        }
        asm volatile("cp.async.commit_group;" ::: "memory");
        compute_stage(kt & 3);
    }

    #pragma unroll
    for (int mt = 0; mt < 4; mt++) {
        const int r0 = m0 + wm * 64 + mt * 16 + (lane >> 2);
        #pragma unroll
        for (int nt = 0; nt < 4; nt++) {
            #pragma unroll
            for (int h = 0; h < 2; h++) {
                const int n = n0 + wn * 64 + nt * 16 + h * 8 + (lane & 3) * 2;
                float2 sf = *reinterpret_cast<const float2*>(wscale + n);
                float2 bf = *reinterpret_cast<const float2*>(wbias + n);
                const float* d = acc[mt][nt*2+h];
                float2 v0, v1;
                v0.x = d[0] * sf.x + bf.x;
                v0.y = d[1] * sf.y + bf.y;
                v1.x = d[2] * sf.x + bf.x;
                v1.y = d[3] * sf.y + bf.y;
                *reinterpret_cast<float2*>(out + (size_t)r0 * NDIM + n) = v0;
                *reinterpret_cast<float2*>(out + (size_t)(r0 + 8) * NDIM + n) = v1;
            }
        }
    }
}

// ---------------------------------------------------------------------------
// Host
// ---------------------------------------------------------------------------
extern "C" void kernel_launch(void* const* d_in, const int* in_sizes, int n_in,
                              void* d_out, int out_size) {
    const float* x  = (const float*)d_in[0];
    const int*   wq = (const int*)d_in[1];
    const float* sc = (const float*)d_in[2];
    const float* bi = (const float*)d_in[3];
    float* out = (float*)d_out;

    convert_fused_kernel<<<NX_BLOCKS + NW_BLOCKS, CV_THREADS>>>(
        (const float4*)x, (const int4*)wq);

    cudaFuncSetAttribute(qlinear_gemm, cudaFuncAttributeMaxDynamicSharedMemorySize, SMEM_TOTAL);
    dim3 grid(NDIM / BN, MDIM / BM);   // (86, 32), n-fastest for W L2 reuse
    qlinear_gemm<<<grid, 256, SMEM_TOTAL>>>(sc, bi, out);
}

// round 15
// speedup vs baseline: 4.4307x; 1.0337x over previous
#include <cuda_runtime.h>
#include <cuda_bf16.h>
#include <cuda_fp16.h>
#include <cstdint>

// Problem dims
#define MDIM 8192
#define KDIM 4096
#define NDIM 11008

// Tiling: CTA 256x128x64, 16 warps as 8(M) x 2(N), warp tile 32x64
#define BM 256
#define BN 128
#define BK 64
#define KT (KDIM / BK)        // 64 k-tiles
#define STAGES 4

// Padded smem: rows of 64 fp16 padded to 72 (144B) for conflict-free ldmatrix
#define PITCH_B 144
#define A_TILE_B (BM * PITCH_B)          // 36864
#define W_TILE_B (BN * PITCH_B)          // 18432
#define STAGE_B  (A_TILE_B + W_TILE_B)   // 55296
#define SMEM_TOTAL (STAGES * STAGE_B)    // 221184

// Fused convert kernel work split
#define NX_ITEMS (MDIM * KDIM / 4)                    // float4 items for X
#define NW_ITEMS ((size_t)NDIM * KDIM / 16)           // 16-int groups for W
#define CV_THREADS 256
#define NX_BLOCKS ((NX_ITEMS + CV_THREADS - 1) / CV_THREADS)
#define NW_BLOCKS ((unsigned)((NW_ITEMS + CV_THREADS - 1) / CV_THREADS))

// ---------------------------------------------------------------------------
// Static scratch (no allocs allowed)
// ---------------------------------------------------------------------------
__device__ __half g_X[(size_t)MDIM * KDIM];
__device__ __half g_W[(size_t)NDIM * KDIM];

__device__ __forceinline__ uint32_t smem_u32(const void* p) {
    uint32_t a;
    asm("{ .reg .u64 t; cvta.to.shared.u64 t, %1; cvt.u32.u64 %0, t; }" : "=r"(a) : "l"(p));
    return a;
}

__device__ __forceinline__ void cp16(uint32_t s, const void* g) {
    asm volatile("cp.async.cg.shared.global [%0], [%1], 16;" :: "r"(s), "l"(g));
}

__device__ __forceinline__ void ldsm4(uint32_t* r, uint32_t a) {
    asm volatile("ldmatrix.sync.aligned.m8n8.x4.shared.b16 {%0,%1,%2,%3}, [%4];"
                 : "=r"(r[0]), "=r"(r[1]), "=r"(r[2]), "=r"(r[3]) : "r"(a));
}

__device__ __forceinline__ void mma16816(float* d, const uint32_t* a, uint32_t b0, uint32_t b1) {
    asm volatile(
        "mma.sync.aligned.m16n8k16.row.col.f32.f16.f16.f32 "
        "{%0,%1,%2,%3}, {%4,%5,%6,%7}, {%8,%9}, {%0,%1,%2,%3};"
        : "+f"(d[0]), "+f"(d[1]), "+f"(d[2]), "+f"(d[3])
        : "r"(a[0]), "r"(a[1]), "r"(a[2]), "r"(a[3]), "r"(b0), "r"(b1));
}

// ---------------------------------------------------------------------------
// Fused pre-pass: one launch converts X (fp32 -> fp16) and W (int32 -> fp16)
// ---------------------------------------------------------------------------
__global__ void __launch_bounds__(CV_THREADS) convert_fused_kernel(
    const float4* __restrict__ x, const int4* __restrict__ w)
{
    const unsigned b = blockIdx.x;
    if (b < NX_BLOCKS) {
        const int i = b * CV_THREADS + threadIdx.x;
        if (i >= NX_ITEMS) return;
        float4 v = x[i];
        __half2 a2, b2;
        a2.x = __float2half_rn(v.x); a2.y = __float2half_rn(v.y);
        b2.x = __float2half_rn(v.z); b2.y = __float2half_rn(v.w);
        __half2* xp = reinterpret_cast<__half2*>(g_X);
        xp[2*i] = a2; xp[2*i+1] = b2;
    } else {
        const size_t i = (size_t)(b - NX_BLOCKS) * CV_THREADS + threadIdx.x;
        if (i >= NW_ITEMS) return;
        __half2 h[8];
        #pragma unroll
        for (int j = 0; j < 4; j++) {
            int4 v = w[i * 4 + j];
            h[2*j+0].x = __float2half_rn((float)v.x);
            h[2*j+0].y = __float2half_rn((float)v.y);
            h[2*j+1].x = __float2half_rn((float)v.z);
            h[2*j+1].y = __float2half_rn((float)v.w);
        }
        uint4* wp = reinterpret_cast<uint4*>(g_W);
        const uint32_t* hr = reinterpret_cast<const uint32_t*>(h);
        wp[2*i]   = make_uint4(hr[0], hr[1], hr[2], hr[3]);
        wp[2*i+1] = make_uint4(hr[4], hr[5], hr[6], hr[7]);
    }
}

// ---------------------------------------------------------------------------
// Main GEMM: mma.sync fp16, cp.async 4-stage pipeline
// 512 threads = 16 warps (4/SMSP for latency hiding), warp tile 32x64
// ---------------------------------------------------------------------------
__global__ void __launch_bounds__(512, 1)
qlinear_gemm(const float* __restrict__ wscale,
             const float* __restrict__ wbias,
             float* __restrict__ out)
{
    extern __shared__ char smem[];
    const uint32_t sb = smem_u32(smem);
    const int tid = threadIdx.x;
    const int wid = tid >> 5;
    const int lane = tid & 31;
    const int m0 = blockIdx.y * BM;
    const int n0 = blockIdx.x * BN;
    const int wm = wid >> 1;   // 0..7 -> 32 rows each
    const int wn = wid & 1;    // 0..1 -> 64 cols each

    const __half* gX = g_X + (size_t)m0 * KDIM;
    const __half* gW = g_W + (size_t)n0 * KDIM;

    float acc[2][8][4];
    #pragma unroll
    for (int a = 0; a < 2; a++)
        #pragma unroll
        for (int b = 0; b < 8; b++)
            #pragma unroll
            for (int c = 0; c < 4; c++) acc[a][b][c] = 0.f;

    // loads: A 2048 + W 1024 16B-chunks per stage / 512 threads = 6 each
    const int lrow0 = tid >> 3;       // 0..63
    const int lcol  = tid & 7;        // 16B chunk within 128B row

    auto load_stage = [&](int s, int kt) {
        const uint32_t base = sb + s * STAGE_B;
        const int k0 = kt * BK;
        #pragma unroll
        for (int i = 0; i < 4; i++) {
            const int r = lrow0 + i * 64;
            cp16(base + r * PITCH_B + lcol * 16, gX + (size_t)r * KDIM + k0 + lcol * 8);
        }
        #pragma unroll
        for (int i = 0; i < 2; i++) {
            const int r = lrow0 + i * 64;
            cp16(base + A_TILE_B + r * PITCH_B + lcol * 16, gW + (size_t)r * KDIM + k0 + lcol * 8);
        }
    };

    auto compute_stage = [&](int s) {
        const uint32_t abase = sb + s * STAGE_B;
        const uint32_t bbase = abase + A_TILE_B;
        const int lr = lane & 15;
        const int lk = (lane >> 4) * 16;
        #pragma unroll
        for (int ks = 0; ks < 4; ks++) {
            uint32_t af[2][4], bf[4][4];
            #pragma unroll
            for (int mt = 0; mt < 2; mt++) {
                uint32_t ro = (uint32_t)(wm * 32 + mt * 16 + lr) * PITCH_B + ks * 32 + lk;
                ldsm4(af[mt], abase + ro);
            }
            #pragma unroll
            for (int nt = 0; nt < 4; nt++) {
                uint32_t ro = (uint32_t)(wn * 64 + nt * 16 + lr) * PITCH_B + ks * 32 + lk;
                ldsm4(bf[nt], bbase + ro);
            }
            #pragma unroll
            for (int mt = 0; mt < 2; mt++) {
                #pragma unroll
                for (int nt = 0; nt < 4; nt++) {
                    mma16816(acc[mt][nt*2+0], af[mt], bf[nt][0], bf[nt][2]);
                    mma16816(acc[mt][nt*2+1], af[mt], bf[nt][1], bf[nt][3]);
                }
            }
        }
    };

    load_stage(0, 0);
    asm volatile("cp.async.commit_group;" ::: "memory");
    load_stage(1, 1);
    asm volatile("cp.async.commit_group;" ::: "memory");
    load_stage(2, 2);
    asm volatile("cp.async.commit_group;" ::: "memory");

    for (int kt = 0; kt < KT; kt++) {
        asm volatile("cp.async.wait_group 2;" ::: "memory");
        __syncthreads();
        if (kt + 3 < KT) {
            load_stage((kt + 3) & 3, kt + 3);
        }
        asm volatile("cp.async.commit_group;" ::: "memory");
        compute_stage(kt & 3);
    }

    // Epilogue: scale + bias (fp32 inputs), fp32 store
    #pragma unroll
    for (int mt = 0; mt < 2; mt++) {
        const int r0 = m0 + wm * 32 + mt * 16 + (lane >> 2);
        #pragma unroll
        for (int nt = 0; nt < 4; nt++) {
            #pragma unroll
            for (int h = 0; h < 2; h++) {
                const int n = n0 + wn * 64 + nt * 16 + h * 8 + (lane & 3) * 2;
                float2 sf = *reinterpret_cast<const float2*>(wscale + n);
                float2 bf = *reinterpret_cast<const float2*>(wbias + n);
                const float* d = acc[mt][nt*2+h];
                float2 v0, v1;
                v0.x = d[0] * sf.x + bf.x;
                v0.y = d[1] * sf.y + bf.y;
                v1.x = d[2] * sf.x + bf.x;
                v1.y = d[3] * sf.y + bf.y;
                *reinterpret_cast<float2*>(out + (size_t)r0 * NDIM + n) = v0;
                *reinterpret_cast<float2*>(out + (size_t)(r0 + 8) * NDIM + n) = v1;
            }
        }
    }
}

// ---------------------------------------------------------------------------
// Host
// ---------------------------------------------------------------------------
extern "C" void kernel_launch(void* const* d_in, const int* in_sizes, int n_in,
                              void* d_out, int out_size) {
    const float* x  = (const float*)d_in[0];
    const int*   wq = (const int*)d_in[1];
    const float* sc = (const float*)d_in[2];
    const float* bi = (const float*)d_in[3];
    float* out = (float*)d_out;

    convert_fused_kernel<<<NX_BLOCKS + NW_BLOCKS, CV_THREADS>>>(
        (const float4*)x, (const int4*)wq);

    cudaFuncSetAttribute(qlinear_gemm, cudaFuncAttributeMaxDynamicSharedMemorySize, SMEM_TOTAL);
    dim3 grid(NDIM / BN, MDIM / BM);   // (86, 32), n-fastest for W L2 reuse
    qlinear_gemm<<<grid, 512, SMEM_TOTAL>>>(sc, bi, out);
}